// round 12
// baseline (speedup 1.0000x reference)
#include <cuda_runtime.h>

#define C_IN 256
#define O_OUT 256
#define CKTOT 2304   // C_IN * 9

// Transposed deform weights: wT[ck][o], ck = c*9+k.
// UNITS: row = 256 floats = 1024 B = 64 float4.
// +1 padding row so phase-2 prefetch may safely read one row past the end.
__device__ float g_wT_T[(CKTOT + 1) * O_OUT];
__device__ float g_wT_S[(CKTOT + 1) * O_OUT];

// Split-C partial sums for the offset convs (G=8 both).
__device__ float g_part_S[8 * 16 * 18 * 1024];
__device__ float g_part_T[8 * 16 * 18 * 256];

// ---------------------------------------------------------------------------
// Merged weight transpose: w[o][c][3][3] -> wT[c*9+k][o]
// grid = 2*CKTOT blocks; first CKTOT = T branch, rest = S branch.
// ---------------------------------------------------------------------------
__global__ void transpose_w_kernel(const float* __restrict__ wT_src,
                                   const float* __restrict__ wS_src) {
    int blk = blockIdx.x;
    const float* w = (blk < CKTOT) ? wT_src : wS_src;
    float* wT      = (blk < CKTOT) ? g_wT_T : g_wT_S;
    int ck = (blk < CKTOT) ? blk : blk - CKTOT;
    int o = threadIdx.x;
    wT[ck * O_OUT + o] = w[o * CKTOT + ck];
}

// ---------------------------------------------------------------------------
// Offset conv partial: 3x3, stride 1, pad 1, CG-channel slice of 256->18.
// ---------------------------------------------------------------------------
template <int H, int W, int G>
__device__ __forceinline__ void offset_conv_part_body(
    const float* __restrict__ x, const float* __restrict__ wgt,
    float* __restrict__ part, int blk,
    float* sx /*8*324*/, float* sw /*18*72*/)
{
    const int HW = H * W;
    const int tiles = (H / 16) * (W / 16);
    const int CG = C_IN / G;

    const int b    = blk / (tiles * G);
    int rem        = blk % (tiles * G);
    const int tile = rem / G;
    const int g    = rem % G;
    const int h0 = (tile / (W / 16)) * 16;
    const int w0 = (tile % (W / 16)) * 16;
    const int c_start = g * CG;

    const int tid = threadIdx.x;
    const int ty = tid >> 4, tx = tid & 15;

    float acc[18];
#pragma unroll
    for (int i = 0; i < 18; i++) acc[i] = 0.f;

    const float* xb = x + (size_t)b * C_IN * HW;

    for (int c0 = c_start; c0 < c_start + CG; c0 += 8) {
        __syncthreads();
        for (int e = tid; e < 8 * 324; e += 256) {
            int c = e / 324, r = e % 324;
            int yy = r / 18 - 1 + h0;
            int xx = r % 18 - 1 + w0;
            float v = 0.f;
            if (yy >= 0 && yy < H && xx >= 0 && xx < W)
                v = xb[(c0 + c) * HW + yy * W + xx];
            sx[e] = v;
        }
        for (int e = tid; e < 18 * 72; e += 256) {
            int oc = e / 72, r = e % 72;
            sw[e] = wgt[oc * CKTOT + c0 * 9 + r];
        }
        __syncthreads();

#pragma unroll
        for (int c = 0; c < 8; c++) {
            float xv[9];
#pragma unroll
            for (int t = 0; t < 9; t++)
                xv[t] = sx[c * 324 + (ty + t / 3) * 18 + (tx + t % 3)];
#pragma unroll
            for (int oc = 0; oc < 18; oc++) {
#pragma unroll
                for (int t = 0; t < 9; t++)
                    acc[oc] += xv[t] * sw[oc * 72 + c * 9 + t];
            }
        }
    }

    const int h = h0 + ty, w = w0 + tx;
    float* ob = part + (size_t)g * 16 * 18 * HW + (size_t)b * 18 * HW + h * W + w;
#pragma unroll
    for (int oc = 0; oc < 18; oc++)
        ob[oc * HW] = acc[oc];
}

// Merged: blocks 0..511 = search (32x32), 512..639 = kernel (16x16).
__global__ void __launch_bounds__(256) offset_conv_merged_kernel(
    const float* __restrict__ xT, const float* __restrict__ wgtT,
    const float* __restrict__ xS, const float* __restrict__ wgtS)
{
    __shared__ float sx[8 * 324];
    __shared__ float sw[18 * 72];
    int blk = blockIdx.x;
    if (blk < 512)
        offset_conv_part_body<32, 32, 8>(xS, wgtS, g_part_S, blk, sx, sw);
    else
        offset_conv_part_body<16, 16, 8>(xT, wgtT, g_part_T, blk - 512, sx, sw);
}

// ---------------------------------------------------------------------------
// Merged reduce partials + bias -> final offset tensors (d_out regions).
// ---------------------------------------------------------------------------
__global__ void reduce_offset_merged_kernel(
    const float* __restrict__ biasT, float* __restrict__ outT,
    const float* __restrict__ biasS, float* __restrict__ outS)
{
    int i = blockIdx.x * 256 + threadIdx.x;
    const float* part;
    const float* bias;
    float* out;
    int perG, HW, idx;
    if (i < 73728) {
        part = g_part_T; bias = biasT; out = outT;
        perG = 73728; HW = 256; idx = i;
    } else {
        if (i >= 368640) return;
        part = g_part_S; bias = biasS; out = outS;
        perG = 294912; HW = 1024; idx = i - 73728;
    }
    float s = 0.f;
#pragma unroll
    for (int g = 0; g < 8; g++) s += part[(size_t)g * perG + idx];
    int oc = (idx / HW) % 18;
    out[idx] = s + bias[oc];
}

// ---------------------------------------------------------------------------
// Deformable conv v1 (3x3, pad 1, 1 group, no bias). P=32 pixels per block.
// Channel chunk = 32 (8 chunks); smem = 46,080 B -> 4 CTAs/SM (32 warps).
// Phase 0: bilinear corner idx/weights (float4/int4) -> smem.
// Phase 1: gather samp[288][32] per chunk (2-element unroll for LDG MLP).
// Phase 2: thread = 4 out-ch x 8 pixels; f32x2 FMAs + weight prefetch.
// ---------------------------------------------------------------------------
template <int H, int W>
__device__ __forceinline__ void deform_conv_body(
    const float* __restrict__ x, const float* __restrict__ off,
    const float* __restrict__ wT, float* __restrict__ out,
    int blk, float* smem)
{
    const int HW = H * W;
    const int nT = HW / 32;
    const int b = blk / nT;
    const int tileBase = (blk % nT) * 32;

    float*  samp = smem;                               // 288*32 floats = 36,864 B
    float4* cWv  = (float4*)(smem + 288 * 32);         // 288 float4
    int4*   cIv  = (int4*)(cWv + 288);                 // 288 int4

    const int tid = threadIdx.x;

    // ---- Phase 0: bilinear corners for 9 taps x 32 positions ----
    for (int e = tid; e < 288; e += 256) {
        int k = e >> 5, p = e & 31;
        int pos = tileBase + p;
        int h = pos / W, w = pos % W;
        const float* ob = off + (size_t)b * 18 * HW + pos;
        float dy = ob[(2 * k) * HW];
        float dx = ob[(2 * k + 1) * HW];
        float sy = (float)(h + k / 3 - 1) + dy;
        float sx = (float)(w + k % 3 - 1) + dx;
        float fy = floorf(sy), fx = floorf(sx);
        int iy = (int)fy, ix = (int)fx;
        float ly = sy - fy, lx = sx - fx;
        float wb[4];
        wb[0] = (1.f - ly) * (1.f - lx);
        wb[1] = (1.f - ly) * lx;
        wb[2] = ly * (1.f - lx);
        wb[3] = ly * lx;
        int ic[4];
        float wc[4];
#pragma unroll
        for (int j = 0; j < 4; j++) {
            int yy = iy + (j >> 1);
            int xx = ix + (j & 1);
            bool ok = (yy >= 0) && (yy < H) && (xx >= 0) && (xx < W);
            int yc = min(max(yy, 0), H - 1);
            int xc = min(max(xx, 0), W - 1);
            ic[j] = yc * W + xc;
            wc[j] = ok ? wb[j] : 0.f;
        }
        cWv[e] = make_float4(wc[0], wc[1], wc[2], wc[3]);
        cIv[e] = make_int4(ic[0], ic[1], ic[2], ic[3]);
    }

    const int pG = tid >> 6;   // 0..3 -> pixels pG*8..+7
    const int oG = tid & 63;   // 0..63 -> channels 4oG..4oG+3

    unsigned long long acc2[16];   // [j][i2]: j = out-ch 0..3, i2 = pixel pair 0..3
#pragma unroll
    for (int i = 0; i < 16; i++) acc2[i] = 0ULL;

    const float* xb = x + (size_t)b * C_IN * HW;

    for (int c0 = 0; c0 < C_IN; c0 += 32) {
        __syncthreads();

        // ---- Phase 1: gather (32 ch x 9 taps) x 32 positions ----
        // 288*32/256 = 36 elements per thread, statically known; process in
        // pairs so the 8 corner LDGs of two elements are in flight together.
#pragma unroll 2
        for (int it = 0; it < 18; it++) {
            int e0 = tid + (2 * it) * 256;
            int e1 = e0 + 256;
            int ck0 = e0 >> 5, p0 = e0 & 31;
            int ck1 = e1 >> 5, p1 = e1 & 31;
            int cq0 = ck0 / 9, k0 = ck0 - cq0 * 9;
            int cq1 = ck1 / 9, k1 = ck1 - cq1 * 9;
            const float* xc0 = xb + (c0 + cq0) * HW;
            const float* xc1 = xb + (c0 + cq1) * HW;
            float4 w40 = cWv[k0 * 32 + p0];
            int4   i40 = cIv[k0 * 32 + p0];
            float4 w41 = cWv[k1 * 32 + p1];
            int4   i41 = cIv[k1 * 32 + p1];
            float a0 = __ldg(xc0 + i40.x), a1 = __ldg(xc0 + i40.y);
            float a2 = __ldg(xc0 + i40.z), a3 = __ldg(xc0 + i40.w);
            float b0 = __ldg(xc1 + i41.x), b1 = __ldg(xc1 + i41.y);
            float b2 = __ldg(xc1 + i41.z), b3 = __ldg(xc1 + i41.w);
            samp[e0] = w40.x * a0 + w40.y * a1 + w40.z * a2 + w40.w * a3;
            samp[e1] = w41.x * b0 + w41.y * b1 + w41.z * b2 + w41.w * b3;
        }
        __syncthreads();

        // ---- Phase 2: f32x2 GEMM with weight prefetch ----
        // UNITS: wT row = 256 floats = 64 float4; wp bump = +64/ckl.
        //        samp row = 32 floats = 8 ulonglong2; sp bump = +8/ckl.
        // Prefetch reads one row past the chunk; g_wT_* has +1 padding row.
        const float4* wp = (const float4*)(wT + (size_t)(c0 * 9) * O_OUT) + oG;
        const ulonglong2* sp = (const ulonglong2*)(samp + pG * 8);
        float4 w_cur = __ldg(wp); wp += 64;
#pragma unroll 4
        for (int ckl = 0; ckl < 288; ckl++) {
            float4 w_nxt = __ldg(wp); wp += 64;        // prefetch next ckl
            ulonglong2 sA = sp[0];                     // pixels pG*8+0..3
            ulonglong2 sB = sp[1];  sp += 8;           // pixels pG*8+4..7
            unsigned long long w2[4];
            asm("mov.b64 %0, {%1, %1};" : "=l"(w2[0]) : "r"(__float_as_uint(w_cur.x)));
            asm("mov.b64 %0, {%1, %1};" : "=l"(w2[1]) : "r"(__float_as_uint(w_cur.y)));
            asm("mov.b64 %0, {%1, %1};" : "=l"(w2[2]) : "r"(__float_as_uint(w_cur.z)));
            asm("mov.b64 %0, {%1, %1};" : "=l"(w2[3]) : "r"(__float_as_uint(w_cur.w)));
#pragma unroll
            for (int j = 0; j < 4; j++) {
                asm("fma.rn.f32x2 %0, %1, %2, %0;" : "+l"(acc2[j * 4 + 0]) : "l"(w2[j]), "l"(sA.x));
                asm("fma.rn.f32x2 %0, %1, %2, %0;" : "+l"(acc2[j * 4 + 1]) : "l"(w2[j]), "l"(sA.y));
                asm("fma.rn.f32x2 %0, %1, %2, %0;" : "+l"(acc2[j * 4 + 2]) : "l"(w2[j]), "l"(sB.x));
                asm("fma.rn.f32x2 %0, %1, %2, %0;" : "+l"(acc2[j * 4 + 3]) : "l"(w2[j]), "l"(sB.y));
            }
            w_cur = w_nxt;
        }
    }

    // ---- Epilogue: stage through smem (o x p, pad 33) for coalesced stores ----
    __syncthreads();
    float* sAcc = smem;   // 256*33 = 8448 floats = 33.8 KB <= samp area (36.9 KB)
#pragma unroll
    for (int j = 0; j < 4; j++) {
        int o = oG * 4 + j;
#pragma unroll
        for (int i2 = 0; i2 < 4; i2++) {
            unsigned lo, hi;
            asm("mov.b64 {%0, %1}, %2;" : "=r"(lo), "=r"(hi) : "l"(acc2[j * 4 + i2]));
            sAcc[o * 33 + pG * 8 + 2 * i2 + 0] = __uint_as_float(lo);
            sAcc[o * 33 + pG * 8 + 2 * i2 + 1] = __uint_as_float(hi);
        }
    }
    __syncthreads();

    float* ob = out + (size_t)b * O_OUT * HW + tileBase;
    const int po = tid & 31;
    const int ro = tid >> 5;
#pragma unroll 8
    for (int r = 0; r < 32; r++) {
        int o = r * 8 + ro;
        ob[(size_t)o * HW + po] = sAcc[o * 33 + po];
    }
}

// Merged: blocks 0..511 = search (32x32), 512..639 = kernel (16x16).
__global__ void __launch_bounds__(256, 4) deform_conv_merged_kernel(
    const float* __restrict__ xT, const float* __restrict__ offT, float* __restrict__ outT,
    const float* __restrict__ xS, const float* __restrict__ offS, float* __restrict__ outS)
{
    extern __shared__ float smem[];
    int blk = blockIdx.x;
    if (blk < 512)
        deform_conv_body<32, 32>(xS, offS, g_wT_S, outS, blk, smem);
    else
        deform_conv_body<16, 16>(xT, offT, g_wT_T, outT, blk - 512, smem);
}

// ---------------------------------------------------------------------------
// Launch
// ---------------------------------------------------------------------------
extern "C" void kernel_launch(void* const* d_in, const int* in_sizes, int n_in,
                              void* d_out, int out_size)
{
    const float* kernel_in = (const float*)d_in[0];  // 16x256x16x16
    const float* search_in = (const float*)d_in[1];  // 16x256x32x32
    const float* Toffset_w = (const float*)d_in[2];  // 18x256x3x3
    const float* Toffset_b = (const float*)d_in[3];  // 18
    const float* Tdeform_w = (const float*)d_in[4];  // 256x256x3x3
    const float* Soffset_w = (const float*)d_in[5];
    const float* Soffset_b = (const float*)d_in[6];
    const float* Sdeform_w = (const float*)d_in[7];

    float* out = (float*)d_out;
    float* kout = out;                       // 16*256*16*16 = 1,048,576
    float* sout = out + 1048576;             // 16*256*32*32 = 4,194,304
    float* koff = out + 5242880;             // 16*18*16*16  = 73,728
    float* soff = out + 5316608;             // 16*18*32*32  = 294,912

    const int smemD = (288 * 32) * 4 + 288 * 16 + 288 * 16;   // 46,080 B
    static int attr_done = 0;
    if (!attr_done) {
        cudaFuncSetAttribute((const void*)deform_conv_merged_kernel,
                             cudaFuncAttributeMaxDynamicSharedMemorySize, smemD);
        attr_done = 1;
    }

    // 1) weight transposes (both branches)
    transpose_w_kernel<<<2 * CKTOT, 256>>>(Tdeform_w, Sdeform_w);

    // 2) offset convs (merged, split-C partials)
    offset_conv_merged_kernel<<<640, 256>>>(kernel_in, Toffset_w, search_in, Soffset_w);

    // 3) reduce partials + bias into d_out offset regions (merged)
    reduce_offset_merged_kernel<<<(368640 + 255) / 256, 256>>>(
        Toffset_b, koff, Soffset_b, soff);

    // 4) deformable convs (merged; search blocks first)
    deform_conv_merged_kernel<<<640, 256, smemD>>>(
        kernel_in, koff, kout, search_in, soff, sout);
}

// round 13
// speedup vs baseline: 1.7127x; 1.7127x over previous
#include <cuda_runtime.h>

#define C_IN 256
#define O_OUT 256
#define CKTOT 2304   // C_IN * 9

// Transposed deform weights: wT[ck][o], ck = c*9+k.
// UNITS: row = 256 floats = 1024 B = 64 float4.
// +1 padding row so phase-2 prefetch may safely read one row past the end.
__device__ float g_wT_T[(CKTOT + 1) * O_OUT];
__device__ float g_wT_S[(CKTOT + 1) * O_OUT];

// Split-C partial sums for the offset convs (G=8 both).
__device__ float g_part_S[8 * 16 * 18 * 1024];
__device__ float g_part_T[8 * 16 * 18 * 256];

// ---------------------------------------------------------------------------
// Merged weight transpose: w[o][c][3][3] -> wT[c*9+k][o]
// grid = 2*CKTOT blocks; first CKTOT = T branch, rest = S branch.
// ---------------------------------------------------------------------------
__global__ void transpose_w_kernel(const float* __restrict__ wT_src,
                                   const float* __restrict__ wS_src) {
    int blk = blockIdx.x;
    const float* w = (blk < CKTOT) ? wT_src : wS_src;
    float* wT      = (blk < CKTOT) ? g_wT_T : g_wT_S;
    int ck = (blk < CKTOT) ? blk : blk - CKTOT;
    int o = threadIdx.x;
    wT[ck * O_OUT + o] = w[o * CKTOT + ck];
}

// ---------------------------------------------------------------------------
// Offset conv partial: 3x3, stride 1, pad 1, CG-channel slice of 256->18.
// ---------------------------------------------------------------------------
template <int H, int W, int G>
__device__ __forceinline__ void offset_conv_part_body(
    const float* __restrict__ x, const float* __restrict__ wgt,
    float* __restrict__ part, int blk,
    float* sx /*8*324*/, float* sw /*18*72*/)
{
    const int HW = H * W;
    const int tiles = (H / 16) * (W / 16);
    const int CG = C_IN / G;

    const int b    = blk / (tiles * G);
    int rem        = blk % (tiles * G);
    const int tile = rem / G;
    const int g    = rem % G;
    const int h0 = (tile / (W / 16)) * 16;
    const int w0 = (tile % (W / 16)) * 16;
    const int c_start = g * CG;

    const int tid = threadIdx.x;
    const int ty = tid >> 4, tx = tid & 15;

    float acc[18];
#pragma unroll
    for (int i = 0; i < 18; i++) acc[i] = 0.f;

    const float* xb = x + (size_t)b * C_IN * HW;

    for (int c0 = c_start; c0 < c_start + CG; c0 += 8) {
        __syncthreads();
        for (int e = tid; e < 8 * 324; e += 256) {
            int c = e / 324, r = e % 324;
            int yy = r / 18 - 1 + h0;
            int xx = r % 18 - 1 + w0;
            float v = 0.f;
            if (yy >= 0 && yy < H && xx >= 0 && xx < W)
                v = xb[(c0 + c) * HW + yy * W + xx];
            sx[e] = v;
        }
        for (int e = tid; e < 18 * 72; e += 256) {
            int oc = e / 72, r = e % 72;
            sw[e] = wgt[oc * CKTOT + c0 * 9 + r];
        }
        __syncthreads();

#pragma unroll
        for (int c = 0; c < 8; c++) {
            float xv[9];
#pragma unroll
            for (int t = 0; t < 9; t++)
                xv[t] = sx[c * 324 + (ty + t / 3) * 18 + (tx + t % 3)];
#pragma unroll
            for (int oc = 0; oc < 18; oc++) {
#pragma unroll
                for (int t = 0; t < 9; t++)
                    acc[oc] += xv[t] * sw[oc * 72 + c * 9 + t];
            }
        }
    }

    const int h = h0 + ty, w = w0 + tx;
    float* ob = part + (size_t)g * 16 * 18 * HW + (size_t)b * 18 * HW + h * W + w;
#pragma unroll
    for (int oc = 0; oc < 18; oc++)
        ob[oc * HW] = acc[oc];
}

// Merged: blocks 0..511 = search (32x32), 512..639 = kernel (16x16).
__global__ void __launch_bounds__(256) offset_conv_merged_kernel(
    const float* __restrict__ xT, const float* __restrict__ wgtT,
    const float* __restrict__ xS, const float* __restrict__ wgtS)
{
    __shared__ float sx[8 * 324];
    __shared__ float sw[18 * 72];
    int blk = blockIdx.x;
    if (blk < 512)
        offset_conv_part_body<32, 32, 8>(xS, wgtS, g_part_S, blk, sx, sw);
    else
        offset_conv_part_body<16, 16, 8>(xT, wgtT, g_part_T, blk - 512, sx, sw);
}

// ---------------------------------------------------------------------------
// Merged reduce partials + bias -> final offset tensors (d_out regions).
// ---------------------------------------------------------------------------
__global__ void reduce_offset_merged_kernel(
    const float* __restrict__ biasT, float* __restrict__ outT,
    const float* __restrict__ biasS, float* __restrict__ outS)
{
    int i = blockIdx.x * 256 + threadIdx.x;
    const float* part;
    const float* bias;
    float* out;
    int perG, HW, idx;
    if (i < 73728) {
        part = g_part_T; bias = biasT; out = outT;
        perG = 73728; HW = 256; idx = i;
    } else {
        if (i >= 368640) return;
        part = g_part_S; bias = biasS; out = outS;
        perG = 294912; HW = 1024; idx = i - 73728;
    }
    float s = 0.f;
#pragma unroll
    for (int g = 0; g < 8; g++) s += part[(size_t)g * perG + idx];
    int oc = (idx / HW) % 18;
    out[idx] = s + bias[oc];
}

// ---------------------------------------------------------------------------
// Deformable conv v1 (3x3, pad 1, 1 group, no bias). P=32 pixels per block.
// Channel chunk = 32 (8 chunks); smem = 46,080 B.
// launch_bounds(256,3): ~85 regs -> room for prefetch WITHOUT spilling
// (R12 post-mortem: same code at 64 regs spilled to local, L1% 62, 1222us).
// Phase 0: bilinear corner idx/weights (float4/int4) -> smem.
// Phase 1: gather samp[288][32] per chunk (2-element pairing for LDG MLP).
// Phase 2: thread = 4 out-ch x 8 pixels; f32x2 FMAs + weight prefetch.
// ---------------------------------------------------------------------------
template <int H, int W>
__device__ __forceinline__ void deform_conv_body(
    const float* __restrict__ x, const float* __restrict__ off,
    const float* __restrict__ wT, float* __restrict__ out,
    int blk, float* smem)
{
    const int HW = H * W;
    const int nT = HW / 32;
    const int b = blk / nT;
    const int tileBase = (blk % nT) * 32;

    float*  samp = smem;                               // 288*32 floats = 36,864 B
    float4* cWv  = (float4*)(smem + 288 * 32);         // 288 float4
    int4*   cIv  = (int4*)(cWv + 288);                 // 288 int4

    const int tid = threadIdx.x;

    // ---- Phase 0: bilinear corners for 9 taps x 32 positions ----
    for (int e = tid; e < 288; e += 256) {
        int k = e >> 5, p = e & 31;
        int pos = tileBase + p;
        int h = pos / W, w = pos % W;
        const float* ob = off + (size_t)b * 18 * HW + pos;
        float dy = ob[(2 * k) * HW];
        float dx = ob[(2 * k + 1) * HW];
        float sy = (float)(h + k / 3 - 1) + dy;
        float sx = (float)(w + k % 3 - 1) + dx;
        float fy = floorf(sy), fx = floorf(sx);
        int iy = (int)fy, ix = (int)fx;
        float ly = sy - fy, lx = sx - fx;
        float wb[4];
        wb[0] = (1.f - ly) * (1.f - lx);
        wb[1] = (1.f - ly) * lx;
        wb[2] = ly * (1.f - lx);
        wb[3] = ly * lx;
        int ic[4];
        float wc[4];
#pragma unroll
        for (int j = 0; j < 4; j++) {
            int yy = iy + (j >> 1);
            int xx = ix + (j & 1);
            bool ok = (yy >= 0) && (yy < H) && (xx >= 0) && (xx < W);
            int yc = min(max(yy, 0), H - 1);
            int xc = min(max(xx, 0), W - 1);
            ic[j] = yc * W + xc;
            wc[j] = ok ? wb[j] : 0.f;
        }
        cWv[e] = make_float4(wc[0], wc[1], wc[2], wc[3]);
        cIv[e] = make_int4(ic[0], ic[1], ic[2], ic[3]);
    }

    const int pG = tid >> 6;   // 0..3 -> pixels pG*8..+7
    const int oG = tid & 63;   // 0..63 -> channels 4oG..4oG+3

    unsigned long long acc2[16];   // [j][i2]: j = out-ch 0..3, i2 = pixel pair 0..3
#pragma unroll
    for (int i = 0; i < 16; i++) acc2[i] = 0ULL;

    const float* xb = x + (size_t)b * C_IN * HW;

    for (int c0 = 0; c0 < C_IN; c0 += 32) {
        __syncthreads();

        // ---- Phase 1: gather (32 ch x 9 taps) x 32 positions ----
        // 288*32/256 = 36 elements per thread; paired so 8 corner LDGs of two
        // elements are in flight together.
#pragma unroll 2
        for (int it = 0; it < 18; it++) {
            int e0 = tid + (2 * it) * 256;
            int e1 = e0 + 256;
            int ck0 = e0 >> 5, p0 = e0 & 31;
            int ck1 = e1 >> 5, p1 = e1 & 31;
            int cq0 = ck0 / 9, k0 = ck0 - cq0 * 9;
            int cq1 = ck1 / 9, k1 = ck1 - cq1 * 9;
            const float* xc0 = xb + (c0 + cq0) * HW;
            const float* xc1 = xb + (c0 + cq1) * HW;
            float4 w40 = cWv[k0 * 32 + p0];
            int4   i40 = cIv[k0 * 32 + p0];
            float4 w41 = cWv[k1 * 32 + p1];
            int4   i41 = cIv[k1 * 32 + p1];
            float a0 = __ldg(xc0 + i40.x), a1 = __ldg(xc0 + i40.y);
            float a2 = __ldg(xc0 + i40.z), a3 = __ldg(xc0 + i40.w);
            float b0 = __ldg(xc1 + i41.x), b1 = __ldg(xc1 + i41.y);
            float b2 = __ldg(xc1 + i41.z), b3 = __ldg(xc1 + i41.w);
            samp[e0] = w40.x * a0 + w40.y * a1 + w40.z * a2 + w40.w * a3;
            samp[e1] = w41.x * b0 + w41.y * b1 + w41.z * b2 + w41.w * b3;
        }
        __syncthreads();

        // ---- Phase 2: f32x2 GEMM with weight prefetch ----
        // UNITS: wT row = 256 floats = 64 float4; wp bump = +64/ckl.
        //        samp row = 32 floats = 8 ulonglong2; sp bump = +8/ckl.
        // Prefetch reads one row past the chunk; g_wT_* has +1 padding row.
        const float4* wp = (const float4*)(wT + (size_t)(c0 * 9) * O_OUT) + oG;
        const ulonglong2* sp = (const ulonglong2*)(samp + pG * 8);
        float4 w_cur = __ldg(wp); wp += 64;
#pragma unroll 4
        for (int ckl = 0; ckl < 288; ckl++) {
            float4 w_nxt = __ldg(wp); wp += 64;        // prefetch next ckl
            ulonglong2 sA = sp[0];                     // pixels pG*8+0..3
            ulonglong2 sB = sp[1];  sp += 8;           // pixels pG*8+4..7
            unsigned long long w2[4];
            asm("mov.b64 %0, {%1, %1};" : "=l"(w2[0]) : "r"(__float_as_uint(w_cur.x)));
            asm("mov.b64 %0, {%1, %1};" : "=l"(w2[1]) : "r"(__float_as_uint(w_cur.y)));
            asm("mov.b64 %0, {%1, %1};" : "=l"(w2[2]) : "r"(__float_as_uint(w_cur.z)));
            asm("mov.b64 %0, {%1, %1};" : "=l"(w2[3]) : "r"(__float_as_uint(w_cur.w)));
#pragma unroll
            for (int j = 0; j < 4; j++) {
                asm("fma.rn.f32x2 %0, %1, %2, %0;" : "+l"(acc2[j * 4 + 0]) : "l"(w2[j]), "l"(sA.x));
                asm("fma.rn.f32x2 %0, %1, %2, %0;" : "+l"(acc2[j * 4 + 1]) : "l"(w2[j]), "l"(sA.y));
                asm("fma.rn.f32x2 %0, %1, %2, %0;" : "+l"(acc2[j * 4 + 2]) : "l"(w2[j]), "l"(sB.x));
                asm("fma.rn.f32x2 %0, %1, %2, %0;" : "+l"(acc2[j * 4 + 3]) : "l"(w2[j]), "l"(sB.y));
            }
            w_cur = w_nxt;
        }
    }

    // ---- Epilogue: stage through smem (o x p, pad 33) for coalesced stores ----
    __syncthreads();
    float* sAcc = smem;   // 256*33 = 8448 floats = 33.8 KB <= samp area (36.9 KB)
#pragma unroll
    for (int j = 0; j < 4; j++) {
        int o = oG * 4 + j;
#pragma unroll
        for (int i2 = 0; i2 < 4; i2++) {
            unsigned lo, hi;
            asm("mov.b64 {%0, %1}, %2;" : "=r"(lo), "=r"(hi) : "l"(acc2[j * 4 + i2]));
            sAcc[o * 33 + pG * 8 + 2 * i2 + 0] = __uint_as_float(lo);
            sAcc[o * 33 + pG * 8 + 2 * i2 + 1] = __uint_as_float(hi);
        }
    }
    __syncthreads();

    float* ob = out + (size_t)b * O_OUT * HW + tileBase;
    const int po = tid & 31;
    const int ro = tid >> 5;
#pragma unroll 8
    for (int r = 0; r < 32; r++) {
        int o = r * 8 + ro;
        ob[(size_t)o * HW + po] = sAcc[o * 33 + po];
    }
}

// Merged: blocks 0..511 = search (32x32), 512..639 = kernel (16x16).
// 3 CTAs/SM: ~85 regs available, no spills for prefetch + gather pairing.
__global__ void __launch_bounds__(256, 3) deform_conv_merged_kernel(
    const float* __restrict__ xT, const float* __restrict__ offT, float* __restrict__ outT,
    const float* __restrict__ xS, const float* __restrict__ offS, float* __restrict__ outS)
{
    extern __shared__ float smem[];
    int blk = blockIdx.x;
    if (blk < 512)
        deform_conv_body<32, 32>(xS, offS, g_wT_S, outS, blk, smem);
    else
        deform_conv_body<16, 16>(xT, offT, g_wT_T, outT, blk - 512, smem);
}

// ---------------------------------------------------------------------------
// Launch
// ---------------------------------------------------------------------------
extern "C" void kernel_launch(void* const* d_in, const int* in_sizes, int n_in,
                              void* d_out, int out_size)
{
    const float* kernel_in = (const float*)d_in[0];  // 16x256x16x16
    const float* search_in = (const float*)d_in[1];  // 16x256x32x32
    const float* Toffset_w = (const float*)d_in[2];  // 18x256x3x3
    const float* Toffset_b = (const float*)d_in[3];  // 18
    const float* Tdeform_w = (const float*)d_in[4];  // 256x256x3x3
    const float* Soffset_w = (const float*)d_in[5];
    const float* Soffset_b = (const float*)d_in[6];
    const float* Sdeform_w = (const float*)d_in[7];

    float* out = (float*)d_out;
    float* kout = out;                       // 16*256*16*16 = 1,048,576
    float* sout = out + 1048576;             // 16*256*32*32 = 4,194,304
    float* koff = out + 5242880;             // 16*18*16*16  = 73,728
    float* soff = out + 5316608;             // 16*18*32*32  = 294,912

    const int smemD = (288 * 32) * 4 + 288 * 16 + 288 * 16;   // 46,080 B
    static int attr_done = 0;
    if (!attr_done) {
        cudaFuncSetAttribute((const void*)deform_conv_merged_kernel,
                             cudaFuncAttributeMaxDynamicSharedMemorySize, smemD);
        attr_done = 1;
    }

    // 1) weight transposes (both branches)
    transpose_w_kernel<<<2 * CKTOT, 256>>>(Tdeform_w, Sdeform_w);

    // 2) offset convs (merged, split-C partials)
    offset_conv_merged_kernel<<<640, 256>>>(kernel_in, Toffset_w, search_in, Soffset_w);

    // 3) reduce partials + bias into d_out offset regions (merged)
    reduce_offset_merged_kernel<<<(368640 + 255) / 256, 256>>>(
        Toffset_b, koff, Soffset_b, soff);

    // 4) deformable convs (merged; search blocks first)
    deform_conv_merged_kernel<<<640, 256, smemD>>>(
        kernel_in, koff, kout, search_in, soff, sout);
}

// round 14
// speedup vs baseline: 1.7587x; 1.0269x over previous
#include <cuda_runtime.h>

#define C_IN 256
#define O_OUT 256
#define CKTOT 2304   // C_IN * 9

// Transposed deform weights: wT[ck][o], ck = c*9+k.
// UNITS: row = 256 floats = 1024 B = 64 float4.
// +1 padding row so phase-2 prefetch may safely read one row past the end.
__device__ float g_wT_T[(CKTOT + 1) * O_OUT];
__device__ float g_wT_S[(CKTOT + 1) * O_OUT];

// Split-C partial sums for the offset convs (G=8 both).
__device__ float g_part_S[8 * 16 * 18 * 1024];
__device__ float g_part_T[8 * 16 * 18 * 256];

// ---------------------------------------------------------------------------
// Merged weight transpose: w[o][c][3][3] -> wT[c*9+k][o]
// ---------------------------------------------------------------------------
__global__ void transpose_w_kernel(const float* __restrict__ wT_src,
                                   const float* __restrict__ wS_src) {
    int blk = blockIdx.x;
    const float* w = (blk < CKTOT) ? wT_src : wS_src;
    float* wT      = (blk < CKTOT) ? g_wT_T : g_wT_S;
    int ck = (blk < CKTOT) ? blk : blk - CKTOT;
    int o = threadIdx.x;
    wT[ck * O_OUT + o] = w[o * CKTOT + ck];
}

// ---------------------------------------------------------------------------
// Offset conv partial: 3x3, stride 1, pad 1, CG-channel slice of 256->18.
// ---------------------------------------------------------------------------
template <int H, int W, int G>
__device__ __forceinline__ void offset_conv_part_body(
    const float* __restrict__ x, const float* __restrict__ wgt,
    float* __restrict__ part, int blk,
    float* sx /*8*324*/, float* sw /*18*72*/)
{
    const int HW = H * W;
    const int tiles = (H / 16) * (W / 16);
    const int CG = C_IN / G;

    const int b    = blk / (tiles * G);
    int rem        = blk % (tiles * G);
    const int tile = rem / G;
    const int g    = rem % G;
    const int h0 = (tile / (W / 16)) * 16;
    const int w0 = (tile % (W / 16)) * 16;
    const int c_start = g * CG;

    const int tid = threadIdx.x;
    const int ty = tid >> 4, tx = tid & 15;

    float acc[18];
#pragma unroll
    for (int i = 0; i < 18; i++) acc[i] = 0.f;

    const float* xb = x + (size_t)b * C_IN * HW;

    for (int c0 = c_start; c0 < c_start + CG; c0 += 8) {
        __syncthreads();
        for (int e = tid; e < 8 * 324; e += 256) {
            int c = e / 324, r = e % 324;
            int yy = r / 18 - 1 + h0;
            int xx = r % 18 - 1 + w0;
            float v = 0.f;
            if (yy >= 0 && yy < H && xx >= 0 && xx < W)
                v = xb[(c0 + c) * HW + yy * W + xx];
            sx[e] = v;
        }
        for (int e = tid; e < 18 * 72; e += 256) {
            int oc = e / 72, r = e % 72;
            sw[e] = wgt[oc * CKTOT + c0 * 9 + r];
        }
        __syncthreads();

#pragma unroll
        for (int c = 0; c < 8; c++) {
            float xv[9];
#pragma unroll
            for (int t = 0; t < 9; t++)
                xv[t] = sx[c * 324 + (ty + t / 3) * 18 + (tx + t % 3)];
#pragma unroll
            for (int oc = 0; oc < 18; oc++) {
#pragma unroll
                for (int t = 0; t < 9; t++)
                    acc[oc] += xv[t] * sw[oc * 72 + c * 9 + t];
            }
        }
    }

    const int h = h0 + ty, w = w0 + tx;
    float* ob = part + (size_t)g * 16 * 18 * HW + (size_t)b * 18 * HW + h * W + w;
#pragma unroll
    for (int oc = 0; oc < 18; oc++)
        ob[oc * HW] = acc[oc];
}

// Merged: blocks 0..511 = search (32x32), 512..639 = kernel (16x16).
__global__ void __launch_bounds__(256) offset_conv_merged_kernel(
    const float* __restrict__ xT, const float* __restrict__ wgtT,
    const float* __restrict__ xS, const float* __restrict__ wgtS)
{
    __shared__ float sx[8 * 324];
    __shared__ float sw[18 * 72];
    int blk = blockIdx.x;
    if (blk < 512)
        offset_conv_part_body<32, 32, 8>(xS, wgtS, g_part_S, blk, sx, sw);
    else
        offset_conv_part_body<16, 16, 8>(xT, wgtT, g_part_T, blk - 512, sx, sw);
}

// ---------------------------------------------------------------------------
// Merged reduce partials + bias -> final offset tensors (d_out regions).
// ---------------------------------------------------------------------------
__global__ void reduce_offset_merged_kernel(
    const float* __restrict__ biasT, float* __restrict__ outT,
    const float* __restrict__ biasS, float* __restrict__ outS)
{
    int i = blockIdx.x * 256 + threadIdx.x;
    const float* part;
    const float* bias;
    float* out;
    int perG, HW, idx;
    if (i < 73728) {
        part = g_part_T; bias = biasT; out = outT;
        perG = 73728; HW = 256; idx = i;
    } else {
        if (i >= 368640) return;
        part = g_part_S; bias = biasS; out = outS;
        perG = 294912; HW = 1024; idx = i - 73728;
    }
    float s = 0.f;
#pragma unroll
    for (int g = 0; g < 8; g++) s += part[(size_t)g * perG + idx];
    int oc = (idx / HW) % 18;
    out[idx] = s + bias[oc];
}

// ---------------------------------------------------------------------------
// Deformable conv v1 (3x3, pad 1, 1 group, no bias). P=32 pixels per block.
// Channel chunk = 16 (16 chunks); DOUBLE-BUFFERED samp for gather/GEMM overlap.
// smem: bufA[144*32] | bufB[144*32] | cWv[288 f4] | cIv[288 i4] = 46,080 B.
// launch_bounds(256,3): ~85 regs, no spills (R12 lesson).
// Loop: sync; gather(chunk+1 -> other buf); compute(chunk <- cur buf).
// Warps slip in phase -> gather LDGs (LSU) overlap GEMM FMAs across warps.
// ---------------------------------------------------------------------------
template <int H, int W>
__device__ __forceinline__ void deform_gather_chunk(
    const float* __restrict__ xb, int c0, float* __restrict__ buf,
    const float4* __restrict__ cWv, const int4* __restrict__ cIv, int tid)
{
    const int HW = H * W;
    // 144 ck x 32 p = 4608 elements; 18 per thread; paired for LDG MLP.
#pragma unroll 3
    for (int it = 0; it < 9; it++) {
        int e0 = tid + (2 * it) * 256;
        int e1 = e0 + 256;
        int ck0 = e0 >> 5, p0 = e0 & 31;
        int ck1 = e1 >> 5, p1 = e1 & 31;
        int cq0 = ck0 / 9, k0 = ck0 - cq0 * 9;
        int cq1 = ck1 / 9, k1 = ck1 - cq1 * 9;
        const float* xc0 = xb + (c0 + cq0) * HW;
        const float* xc1 = xb + (c0 + cq1) * HW;
        float4 w40 = cWv[k0 * 32 + p0];
        int4   i40 = cIv[k0 * 32 + p0];
        float4 w41 = cWv[k1 * 32 + p1];
        int4   i41 = cIv[k1 * 32 + p1];
        float a0 = __ldg(xc0 + i40.x), a1 = __ldg(xc0 + i40.y);
        float a2 = __ldg(xc0 + i40.z), a3 = __ldg(xc0 + i40.w);
        float b0 = __ldg(xc1 + i41.x), b1 = __ldg(xc1 + i41.y);
        float b2 = __ldg(xc1 + i41.z), b3 = __ldg(xc1 + i41.w);
        buf[e0] = w40.x * a0 + w40.y * a1 + w40.z * a2 + w40.w * a3;
        buf[e1] = w41.x * b0 + w41.y * b1 + w41.z * b2 + w41.w * b3;
    }
}

template <int H, int W>
__device__ __forceinline__ void deform_conv_body(
    const float* __restrict__ x, const float* __restrict__ off,
    const float* __restrict__ wT, float* __restrict__ out,
    int blk, float* smem)
{
    const int HW = H * W;
    const int nT = HW / 32;
    const int b = blk / nT;
    const int tileBase = (blk % nT) * 32;

    float*  bufA = smem;                               // 144*32 = 4608 floats
    float*  bufB = smem + 4608;                        // 4608 floats
    float4* cWv  = (float4*)(smem + 9216);             // 288 float4
    int4*   cIv  = (int4*)(cWv + 288);                 // 288 int4

    const int tid = threadIdx.x;

    // ---- Phase 0: bilinear corners for 9 taps x 32 positions ----
    for (int e = tid; e < 288; e += 256) {
        int k = e >> 5, p = e & 31;
        int pos = tileBase + p;
        int h = pos / W, w = pos % W;
        const float* ob = off + (size_t)b * 18 * HW + pos;
        float dy = ob[(2 * k) * HW];
        float dx = ob[(2 * k + 1) * HW];
        float sy = (float)(h + k / 3 - 1) + dy;
        float sx = (float)(w + k % 3 - 1) + dx;
        float fy = floorf(sy), fx = floorf(sx);
        int iy = (int)fy, ix = (int)fx;
        float ly = sy - fy, lx = sx - fx;
        float wb[4];
        wb[0] = (1.f - ly) * (1.f - lx);
        wb[1] = (1.f - ly) * lx;
        wb[2] = ly * (1.f - lx);
        wb[3] = ly * lx;
        int ic[4];
        float wc[4];
#pragma unroll
        for (int j = 0; j < 4; j++) {
            int yy = iy + (j >> 1);
            int xx = ix + (j & 1);
            bool ok = (yy >= 0) && (yy < H) && (xx >= 0) && (xx < W);
            int yc = min(max(yy, 0), H - 1);
            int xc = min(max(xx, 0), W - 1);
            ic[j] = yc * W + xc;
            wc[j] = ok ? wb[j] : 0.f;
        }
        cWv[e] = make_float4(wc[0], wc[1], wc[2], wc[3]);
        cIv[e] = make_int4(ic[0], ic[1], ic[2], ic[3]);
    }

    const int pG = tid >> 6;   // 0..3 -> pixels pG*8..+7
    const int oG = tid & 63;   // 0..63 -> channels 4oG..4oG+3

    unsigned long long acc2[16];
#pragma unroll
    for (int i = 0; i < 16; i++) acc2[i] = 0ULL;

    const float* xb = x + (size_t)b * C_IN * HW;

    __syncthreads();                        // corner tables ready
    deform_gather_chunk<H, W>(xb, 0, bufA, cWv, cIv, tid);

    // Weight pointer walks ck-space contiguously across all 16 chunks.
    // UNITS: wT row = 256 floats = 64 float4; bump +64/ckl.
    const float4* wp = (const float4*)wT + oG;
    float4 w_cur;

    for (int chunk = 0; chunk < 16; chunk++) {
        float* bufC = (chunk & 1) ? bufB : bufA;   // compute buffer (gathered)
        float* bufN = (chunk & 1) ? bufA : bufB;   // next gather target
        __syncthreads();                            // bufC writes visible CTA-wide

        if (chunk < 15)
            deform_gather_chunk<H, W>(xb, (chunk + 1) * 16, bufN, cWv, cIv, tid);

        // ---- compute chunk: 144 ckl of f32x2 GEMM with weight prefetch ----
        // UNITS: samp row = 32 floats = 8 ulonglong2; sp bump +8/ckl.
        const ulonglong2* sp = (const ulonglong2*)(bufC + pG * 8);
        w_cur = __ldg(wp); wp += 64;
#pragma unroll 4
        for (int ckl = 0; ckl < 144; ckl++) {
            float4 w_nxt = __ldg(wp); wp += 64;    // prefetch (pad row at very end)
            ulonglong2 sA = sp[0];
            ulonglong2 sB = sp[1];  sp += 8;
            unsigned long long w2[4];
            asm("mov.b64 %0, {%1, %1};" : "=l"(w2[0]) : "r"(__float_as_uint(w_cur.x)));
            asm("mov.b64 %0, {%1, %1};" : "=l"(w2[1]) : "r"(__float_as_uint(w_cur.y)));
            asm("mov.b64 %0, {%1, %1};" : "=l"(w2[2]) : "r"(__float_as_uint(w_cur.z)));
            asm("mov.b64 %0, {%1, %1};" : "=l"(w2[3]) : "r"(__float_as_uint(w_cur.w)));
#pragma unroll
            for (int j = 0; j < 4; j++) {
                asm("fma.rn.f32x2 %0, %1, %2, %0;" : "+l"(acc2[j * 4 + 0]) : "l"(w2[j]), "l"(sA.x));
                asm("fma.rn.f32x2 %0, %1, %2, %0;" : "+l"(acc2[j * 4 + 1]) : "l"(w2[j]), "l"(sA.y));
                asm("fma.rn.f32x2 %0, %1, %2, %0;" : "+l"(acc2[j * 4 + 2]) : "l"(w2[j]), "l"(sB.x));
                asm("fma.rn.f32x2 %0, %1, %2, %0;" : "+l"(acc2[j * 4 + 3]) : "l"(w2[j]), "l"(sB.y));
            }
            w_cur = w_nxt;
        }
        wp -= 64;   // undo the final prefetch advance; next chunk re-reads it
    }

    // ---- Epilogue: stage through smem (o x p, pad 33) for coalesced stores ----
    __syncthreads();
    float* sAcc = smem;   // 256*33 = 8448 floats <= buffers region (9216)
#pragma unroll
    for (int j = 0; j < 4; j++) {
        int o = oG * 4 + j;
#pragma unroll
        for (int i2 = 0; i2 < 4; i2++) {
            unsigned lo, hi;
            asm("mov.b64 {%0, %1}, %2;" : "=r"(lo), "=r"(hi) : "l"(acc2[j * 4 + i2]));
            sAcc[o * 33 + pG * 8 + 2 * i2 + 0] = __uint_as_float(lo);
            sAcc[o * 33 + pG * 8 + 2 * i2 + 1] = __uint_as_float(hi);
        }
    }
    __syncthreads();

    float* ob = out + (size_t)b * O_OUT * HW + tileBase;
    const int po = tid & 31;
    const int ro = tid >> 5;
#pragma unroll 8
    for (int r = 0; r < 32; r++) {
        int o = r * 8 + ro;
        ob[(size_t)o * HW + po] = sAcc[o * 33 + po];
    }
}

// Merged: blocks 0..511 = search (32x32), 512..639 = kernel (16x16).
__global__ void __launch_bounds__(256, 3) deform_conv_merged_kernel(
    const float* __restrict__ xT, const float* __restrict__ offT, float* __restrict__ outT,
    const float* __restrict__ xS, const float* __restrict__ offS, float* __restrict__ outS)
{
    extern __shared__ float smem[];
    int blk = blockIdx.x;
    if (blk < 512)
        deform_conv_body<32, 32>(xS, offS, g_wT_S, outS, blk, smem);
    else
        deform_conv_body<16, 16>(xT, offT, g_wT_T, outT, blk - 512, smem);
}

// ---------------------------------------------------------------------------
// Launch
// ---------------------------------------------------------------------------
extern "C" void kernel_launch(void* const* d_in, const int* in_sizes, int n_in,
                              void* d_out, int out_size)
{
    const float* kernel_in = (const float*)d_in[0];  // 16x256x16x16
    const float* search_in = (const float*)d_in[1];  // 16x256x32x32
    const float* Toffset_w = (const float*)d_in[2];  // 18x256x3x3
    const float* Toffset_b = (const float*)d_in[3];  // 18
    const float* Tdeform_w = (const float*)d_in[4];  // 256x256x3x3
    const float* Soffset_w = (const float*)d_in[5];
    const float* Soffset_b = (const float*)d_in[6];
    const float* Sdeform_w = (const float*)d_in[7];

    float* out = (float*)d_out;
    float* kout = out;                       // 16*256*16*16 = 1,048,576
    float* sout = out + 1048576;             // 16*256*32*32 = 4,194,304
    float* koff = out + 5242880;             // 16*18*16*16  = 73,728
    float* soff = out + 5316608;             // 16*18*32*32  = 294,912

    const int smemD = (2 * 4608) * 4 + 288 * 16 + 288 * 16;   // 46,080 B
    static int attr_done = 0;
    if (!attr_done) {
        cudaFuncSetAttribute((const void*)deform_conv_merged_kernel,
                             cudaFuncAttributeMaxDynamicSharedMemorySize, smemD);
        attr_done = 1;
    }

    // 1) weight transposes (both branches)
    transpose_w_kernel<<<2 * CKTOT, 256>>>(Tdeform_w, Sdeform_w);

    // 2) offset convs (merged, split-C partials)
    offset_conv_merged_kernel<<<640, 256>>>(kernel_in, Toffset_w, search_in, Soffset_w);

    // 3) reduce partials + bias into d_out offset regions (merged)
    reduce_offset_merged_kernel<<<(368640 + 255) / 256, 256>>>(
        Toffset_b, koff, Soffset_b, soff);

    // 4) deformable convs (merged; search blocks first)
    deform_conv_merged_kernel<<<640, 256, smemD>>>(
        kernel_in, koff, kout, search_in, soff, sout);
}

// round 16
// speedup vs baseline: 1.8979x; 1.0791x over previous
#include <cuda_runtime.h>

#define C_IN 256
#define O_OUT 256
#define CKTOT 2304   // C_IN * 9

// Transposed deform weights: wT[ck][o], ck = c*9+k.
// UNITS: row = 256 floats = 1024 B = 64 float4.
// +1 padding row so phase-2 prefetch may safely read one row past the end.
__device__ float g_wT_T[(CKTOT + 1) * O_OUT];
__device__ float g_wT_S[(CKTOT + 1) * O_OUT];

// Split-C partial sums for the offset convs (G=8 both).
__device__ float g_part_S[8 * 16 * 18 * 1024];
__device__ float g_part_T[8 * 16 * 18 * 256];

// Split-K partials for the deform convs: [half][b][o][hw]
__device__ float g_dpart_S[2 * 16 * 256 * 1024];   // 33.5 MB
__device__ float g_dpart_T[2 * 16 * 256 * 256];    // 8.4 MB

// ---------------------------------------------------------------------------
// Merged weight transpose: w[o][c][3][3] -> wT[c*9+k][o]
// ---------------------------------------------------------------------------
__global__ void transpose_w_kernel(const float* __restrict__ wT_src,
                                   const float* __restrict__ wS_src) {
    int blk = blockIdx.x;
    const float* w = (blk < CKTOT) ? wT_src : wS_src;
    float* wT      = (blk < CKTOT) ? g_wT_T : g_wT_S;
    int ck = (blk < CKTOT) ? blk : blk - CKTOT;
    int o = threadIdx.x;
    wT[ck * O_OUT + o] = w[o * CKTOT + ck];
}

// ---------------------------------------------------------------------------
// Offset conv partial: 3x3, stride 1, pad 1, CG-channel slice of 256->18.
// ---------------------------------------------------------------------------
template <int H, int W, int G>
__device__ __forceinline__ void offset_conv_part_body(
    const float* __restrict__ x, const float* __restrict__ wgt,
    float* __restrict__ part, int blk,
    float* sx /*8*324*/, float* sw /*18*72*/)
{
    const int HW = H * W;
    const int tiles = (H / 16) * (W / 16);
    const int CG = C_IN / G;

    const int b    = blk / (tiles * G);
    int rem        = blk % (tiles * G);
    const int tile = rem / G;
    const int g    = rem % G;
    const int h0 = (tile / (W / 16)) * 16;
    const int w0 = (tile % (W / 16)) * 16;
    const int c_start = g * CG;

    const int tid = threadIdx.x;
    const int ty = tid >> 4, tx = tid & 15;

    float acc[18];
#pragma unroll
    for (int i = 0; i < 18; i++) acc[i] = 0.f;

    const float* xb = x + (size_t)b * C_IN * HW;

    for (int c0 = c_start; c0 < c_start + CG; c0 += 8) {
        __syncthreads();
        for (int e = tid; e < 8 * 324; e += 256) {
            int c = e / 324, r = e % 324;
            int yy = r / 18 - 1 + h0;
            int xx = r % 18 - 1 + w0;
            float v = 0.f;
            if (yy >= 0 && yy < H && xx >= 0 && xx < W)
                v = xb[(c0 + c) * HW + yy * W + xx];
            sx[e] = v;
        }
        for (int e = tid; e < 18 * 72; e += 256) {
            int oc = e / 72, r = e % 72;
            sw[e] = wgt[oc * CKTOT + c0 * 9 + r];
        }
        __syncthreads();

#pragma unroll
        for (int c = 0; c < 8; c++) {
            float xv[9];
#pragma unroll
            for (int t = 0; t < 9; t++)
                xv[t] = sx[c * 324 + (ty + t / 3) * 18 + (tx + t % 3)];
#pragma unroll
            for (int oc = 0; oc < 18; oc++) {
#pragma unroll
                for (int t = 0; t < 9; t++)
                    acc[oc] += xv[t] * sw[oc * 72 + c * 9 + t];
            }
        }
    }

    const int h = h0 + ty, w = w0 + tx;
    float* ob = part + (size_t)g * 16 * 18 * HW + (size_t)b * 18 * HW + h * W + w;
#pragma unroll
    for (int oc = 0; oc < 18; oc++)
        ob[oc * HW] = acc[oc];
}

// Merged: blocks 0..511 = search (32x32), 512..639 = kernel (16x16).
__global__ void __launch_bounds__(256) offset_conv_merged_kernel(
    const float* __restrict__ xT, const float* __restrict__ wgtT,
    const float* __restrict__ xS, const float* __restrict__ wgtS)
{
    __shared__ float sx[8 * 324];
    __shared__ float sw[18 * 72];
    int blk = blockIdx.x;
    if (blk < 512)
        offset_conv_part_body<32, 32, 8>(xS, wgtS, g_part_S, blk, sx, sw);
    else
        offset_conv_part_body<16, 16, 8>(xT, wgtT, g_part_T, blk - 512, sx, sw);
}

// ---------------------------------------------------------------------------
// Merged reduce partials + bias -> final offset tensors (d_out regions).
// ---------------------------------------------------------------------------
__global__ void reduce_offset_merged_kernel(
    const float* __restrict__ biasT, float* __restrict__ outT,
    const float* __restrict__ biasS, float* __restrict__ outS)
{
    int i = blockIdx.x * 256 + threadIdx.x;
    const float* part;
    const float* bias;
    float* out;
    int perG, HW, idx;
    if (i < 73728) {
        part = g_part_T; bias = biasT; out = outT;
        perG = 73728; HW = 256; idx = i;
    } else {
        if (i >= 368640) return;
        part = g_part_S; bias = biasS; out = outS;
        perG = 294912; HW = 1024; idx = i - 73728;
    }
    float s = 0.f;
#pragma unroll
    for (int g = 0; g < 8; g++) s += part[(size_t)g * perG + idx];
    int oc = (idx / HW) % 18;
    out[idx] = s + bias[oc];
}

// ---------------------------------------------------------------------------
// Deformable conv v1, SPLIT-K: each block does 128 channels (8 chunks of 16)
// of one 32-pixel tile, writing a partial. P=32 pixels per block.
// Double-buffered samp; smem = 46,080 B; launch_bounds(256,3) ~85 regs.
// ---------------------------------------------------------------------------
template <int H, int W>
__device__ __forceinline__ void deform_gather_chunk(
    const float* __restrict__ xb, int c0, float* __restrict__ buf,
    const float4* __restrict__ cWv, const int4* __restrict__ cIv, int tid)
{
    const int HW = H * W;
    // 144 ck x 32 p = 4608 elements; 18 per thread; paired for LDG MLP.
#pragma unroll 3
    for (int it = 0; it < 9; it++) {
        int e0 = tid + (2 * it) * 256;
        int e1 = e0 + 256;
        int ck0 = e0 >> 5, p0 = e0 & 31;
        int ck1 = e1 >> 5, p1 = e1 & 31;
        int cq0 = ck0 / 9, k0 = ck0 - cq0 * 9;
        int cq1 = ck1 / 9, k1 = ck1 - cq1 * 9;
        const float* xc0 = xb + (c0 + cq0) * HW;
        const float* xc1 = xb + (c0 + cq1) * HW;
        float4 w40 = cWv[k0 * 32 + p0];
        int4   i40 = cIv[k0 * 32 + p0];
        float4 w41 = cWv[k1 * 32 + p1];
        int4   i41 = cIv[k1 * 32 + p1];
        float a0 = __ldg(xc0 + i40.x), a1 = __ldg(xc0 + i40.y);
        float a2 = __ldg(xc0 + i40.z), a3 = __ldg(xc0 + i40.w);
        float b0 = __ldg(xc1 + i41.x), b1 = __ldg(xc1 + i41.y);
        float b2 = __ldg(xc1 + i41.z), b3 = __ldg(xc1 + i41.w);
        buf[e0] = w40.x * a0 + w40.y * a1 + w40.z * a2 + w40.w * a3;
        buf[e1] = w41.x * b0 + w41.y * b1 + w41.z * b2 + w41.w * b3;
    }
}

template <int H, int W>
__device__ __forceinline__ void deform_conv_body(
    const float* __restrict__ x, const float* __restrict__ off,
    const float* __restrict__ wT, float* __restrict__ part,
    int tile, int half, int bnum, float* smem)
{
    const int HW = H * W;
    const int nT = HW / 32;
    const int b = tile / nT;
    const int tileBase = (tile % nT) * 32;
    const int c_base = half * 128;       // channels [c_base, c_base+128)

    float*  bufA = smem;                               // 144*32 = 4608 floats
    float*  bufB = smem + 4608;                        // 4608 floats
    float4* cWv  = (float4*)(smem + 9216);             // 288 float4
    int4*   cIv  = (int4*)(cWv + 288);                 // 288 int4

    const int tid = threadIdx.x;

    // ---- Phase 0: bilinear corners for 9 taps x 32 positions ----
    for (int e = tid; e < 288; e += 256) {
        int k = e >> 5, p = e & 31;
        int pos = tileBase + p;
        int h = pos / W, w = pos % W;
        const float* ob = off + (size_t)b * 18 * HW + pos;
        float dy = ob[(2 * k) * HW];
        float dx = ob[(2 * k + 1) * HW];
        float sy = (float)(h + k / 3 - 1) + dy;
        float sx = (float)(w + k % 3 - 1) + dx;
        float fy = floorf(sy), fx = floorf(sx);
        int iy = (int)fy, ix = (int)fx;
        float ly = sy - fy, lx = sx - fx;
        float wb[4];
        wb[0] = (1.f - ly) * (1.f - lx);
        wb[1] = (1.f - ly) * lx;
        wb[2] = ly * (1.f - lx);
        wb[3] = ly * lx;
        int ic[4];
        float wc[4];
#pragma unroll
        for (int j = 0; j < 4; j++) {
            int yy = iy + (j >> 1);
            int xx = ix + (j & 1);
            bool ok = (yy >= 0) && (yy < H) && (xx >= 0) && (xx < W);
            int yc = min(max(yy, 0), H - 1);
            int xc = min(max(xx, 0), W - 1);
            ic[j] = yc * W + xc;
            wc[j] = ok ? wb[j] : 0.f;
        }
        cWv[e] = make_float4(wc[0], wc[1], wc[2], wc[3]);
        cIv[e] = make_int4(ic[0], ic[1], ic[2], ic[3]);
    }

    const int pG = tid >> 6;   // 0..3 -> pixels pG*8..+7
    const int oG = tid & 63;   // 0..63 -> channels 4oG..4oG+3

    unsigned long long acc2[16];
#pragma unroll
    for (int i = 0; i < 16; i++) acc2[i] = 0ULL;

    const float* xb = x + (size_t)b * C_IN * HW;

    __syncthreads();                        // corner tables ready
    deform_gather_chunk<H, W>(xb, c_base, bufA, cWv, cIv, tid);

    // Weight pointer walks ck-space from half*1152, contiguous over 8 chunks.
    // UNITS: wT row = 256 floats = 64 float4; bump +64/ckl.
    // Prefetch overrun at the end of half 0 reads row 1152 (valid), at the end
    // of half 1 reads the pad row (valid).
    const float4* wp = (const float4*)(wT + (size_t)(c_base * 9) * O_OUT) + oG;
    float4 w_cur;

    for (int chunk = 0; chunk < 8; chunk++) {
        float* bufC = (chunk & 1) ? bufB : bufA;   // compute buffer (gathered)
        float* bufN = (chunk & 1) ? bufA : bufB;   // next gather target
        __syncthreads();                            // bufC writes visible CTA-wide

        if (chunk < 7)
            deform_gather_chunk<H, W>(xb, c_base + (chunk + 1) * 16, bufN, cWv, cIv, tid);

        // ---- compute chunk: 144 ckl of f32x2 GEMM with weight prefetch ----
        // UNITS: samp row = 32 floats = 8 ulonglong2; sp bump +8/ckl.
        const ulonglong2* sp = (const ulonglong2*)(bufC + pG * 8);
        w_cur = __ldg(wp); wp += 64;
#pragma unroll 4
        for (int ckl = 0; ckl < 144; ckl++) {
            float4 w_nxt = __ldg(wp); wp += 64;
            ulonglong2 sA = sp[0];
            ulonglong2 sB = sp[1];  sp += 8;
            unsigned long long w2[4];
            asm("mov.b64 %0, {%1, %1};" : "=l"(w2[0]) : "r"(__float_as_uint(w_cur.x)));
            asm("mov.b64 %0, {%1, %1};" : "=l"(w2[1]) : "r"(__float_as_uint(w_cur.y)));
            asm("mov.b64 %0, {%1, %1};" : "=l"(w2[2]) : "r"(__float_as_uint(w_cur.z)));
            asm("mov.b64 %0, {%1, %1};" : "=l"(w2[3]) : "r"(__float_as_uint(w_cur.w)));
#pragma unroll
            for (int j = 0; j < 4; j++) {
                asm("fma.rn.f32x2 %0, %1, %2, %0;" : "+l"(acc2[j * 4 + 0]) : "l"(w2[j]), "l"(sA.x));
                asm("fma.rn.f32x2 %0, %1, %2, %0;" : "+l"(acc2[j * 4 + 1]) : "l"(w2[j]), "l"(sA.y));
                asm("fma.rn.f32x2 %0, %1, %2, %0;" : "+l"(acc2[j * 4 + 2]) : "l"(w2[j]), "l"(sB.x));
                asm("fma.rn.f32x2 %0, %1, %2, %0;" : "+l"(acc2[j * 4 + 3]) : "l"(w2[j]), "l"(sB.y));
            }
            w_cur = w_nxt;
        }
        wp -= 64;   // undo final prefetch advance; next chunk re-reads it
    }

    // ---- Epilogue: stage through smem (o x p, pad 33), store partial ----
    __syncthreads();
    float* sAcc = smem;   // 256*33 = 8448 floats <= buffers region (9216)
#pragma unroll
    for (int j = 0; j < 4; j++) {
        int o = oG * 4 + j;
#pragma unroll
        for (int i2 = 0; i2 < 4; i2++) {
            unsigned lo, hi;
            asm("mov.b64 {%0, %1}, %2;" : "=r"(lo), "=r"(hi) : "l"(acc2[j * 4 + i2]));
            sAcc[o * 33 + pG * 8 + 2 * i2 + 0] = __uint_as_float(lo);
            sAcc[o * 33 + pG * 8 + 2 * i2 + 1] = __uint_as_float(hi);
        }
    }
    __syncthreads();

    float* ob = part + (size_t)half * bnum * O_OUT * HW
                     + (size_t)b * O_OUT * HW + tileBase;
    const int po = tid & 31;
    const int ro = tid >> 5;
#pragma unroll 8
    for (int r = 0; r < 32; r++) {
        int o = r * 8 + ro;
        ob[(size_t)o * HW + po] = sAcc[o * 33 + po];
    }
}

// Split-K merged deform:
//   blocks 0..1023:   search; tile = blk>>1, half = blk&1  (512 tiles)
//   blocks 1024..1279: kernel; t = blk-1024, tile = t>>1, half = t&1 (128 tiles)
__global__ void __launch_bounds__(256, 3) deform_conv_merged_kernel(
    const float* __restrict__ xT, const float* __restrict__ offT,
    const float* __restrict__ xS, const float* __restrict__ offS)
{
    extern __shared__ float smem[];
    int blk = blockIdx.x;
    if (blk < 1024)
        deform_conv_body<32, 32>(xS, offS, g_wT_S, g_dpart_S, blk >> 1, blk & 1, 16, smem);
    else {
        int t = blk - 1024;
        deform_conv_body<16, 16>(xT, offT, g_wT_T, g_dpart_T, t >> 1, t & 1, 16, smem);
    }
}

// ---------------------------------------------------------------------------
// Reduce deform split-K partials -> d_out. float4-vectorized.
// T: 1,048,576 floats = 262,144 float4.  S: 4,194,304 floats = 1,048,576 float4.
// ---------------------------------------------------------------------------
__global__ void reduce_deform_kernel(float* __restrict__ outT, float* __restrict__ outS)
{
    int i = blockIdx.x * 256 + threadIdx.x;
    if (i < 262144) {
        const float4* p0 = (const float4*)g_dpart_T;
        const float4* p1 = (const float4*)(g_dpart_T + 16 * 256 * 256);
        float4 a = p0[i], c = p1[i];
        ((float4*)outT)[i] = make_float4(a.x + c.x, a.y + c.y, a.z + c.z, a.w + c.w);
    } else {
        int j = i - 262144;
        if (j >= 1048576) return;
        const float4* p0 = (const float4*)g_dpart_S;
        const float4* p1 = (const float4*)(g_dpart_S + 16 * 256 * 1024);
        float4 a = p0[j], c = p1[j];
        ((float4*)outS)[j] = make_float4(a.x + c.x, a.y + c.y, a.z + c.z, a.w + c.w);
    }
}

// ---------------------------------------------------------------------------
// Launch
// ---------------------------------------------------------------------------
extern "C" void kernel_launch(void* const* d_in, const int* in_sizes, int n_in,
                              void* d_out, int out_size)
{
    const float* kernel_in = (const float*)d_in[0];  // 16x256x16x16
    const float* search_in = (const float*)d_in[1];  // 16x256x32x32
    const float* Toffset_w = (const float*)d_in[2];  // 18x256x3x3
    const float* Toffset_b = (const float*)d_in[3];  // 18
    const float* Tdeform_w = (const float*)d_in[4];  // 256x256x3x3
    const float* Soffset_w = (const float*)d_in[5];
    const float* Soffset_b = (const float*)d_in[6];
    const float* Sdeform_w = (const float*)d_in[7];

    float* out = (float*)d_out;
    float* kout = out;                       // 16*256*16*16 = 1,048,576
    float* sout = out + 1048576;             // 16*256*32*32 = 4,194,304
    float* koff = out + 5242880;             // 16*18*16*16  = 73,728
    float* soff = out + 5316608;             // 16*18*32*32  = 294,912

    const int smemD = (2 * 4608) * 4 + 288 * 16 + 288 * 16;   // 46,080 B
    static int attr_done = 0;
    if (!attr_done) {
        cudaFuncSetAttribute((const void*)deform_conv_merged_kernel,
                             cudaFuncAttributeMaxDynamicSharedMemorySize, smemD);
        attr_done = 1;
    }

    // 1) weight transposes (both branches)
    transpose_w_kernel<<<2 * CKTOT, 256>>>(Tdeform_w, Sdeform_w);

    // 2) offset convs (merged, split-C partials)
    offset_conv_merged_kernel<<<640, 256>>>(kernel_in, Toffset_w, search_in, Soffset_w);

    // 3) reduce partials + bias into d_out offset regions (merged)
    reduce_offset_merged_kernel<<<(368640 + 255) / 256, 256>>>(
        Toffset_b, koff, Soffset_b, soff);

    // 4) deformable convs (split-K, 1280 blocks)
    deform_conv_merged_kernel<<<1280, 256, smemD>>>(
        kernel_in, koff, search_in, soff);

    // 5) reduce deform partials -> final outputs
    reduce_deform_kernel<<<(1310720 + 255) / 256, 256>>>(kout, sout);
}